// round 4
// baseline (speedup 1.0000x reference)
#include <cuda_runtime.h>
#include <math.h>

#define LTOK 65536          // H*W tokens
#define CDIM 192
#define NHEADS 6
#define HDIM 32
#define HIDD 768

typedef unsigned long long ull;

// -------- scratch (static device globals; no allocation) --------
__device__ float g_xw[LTOK * CDIM];       // LN1'd, shifted, window-partitioned; reused as y0 after QKV
__device__ float g_q[LTOK * CDIM];        // [win,head,n,d]
__device__ float g_k[LTOK * CDIM];
__device__ float g_v[LTOK * CDIM];
__device__ float g_ao[LTOK * CDIM];       // attention out, window order, col = head*32+d
__device__ float g_xr[LTOK * CDIM];       // first residual, token order
__device__ float g_h[LTOK * HIDD];        // MLP hidden
__device__ float g_bias6[NHEADS * 256 * 256];

// -------- packed f32x2 helpers --------
__device__ __forceinline__ ull pk2(float lo, float hi) {
    ull r; asm("mov.b64 %0, {%1,%2};" : "=l"(r) : "f"(lo), "f"(hi)); return r;
}
__device__ __forceinline__ float2 upk(ull v) {
    float2 f; asm("mov.b64 {%0,%1}, %2;" : "=f"(f.x), "=f"(f.y) : "l"(v)); return f;
}
#define FMA2(d, a, b, c) asm("fma.rn.f32x2 %0, %1, %2, %3;" : "=l"(d) : "l"(a), "l"(b), "l"(c))
#define MUL2(d, a, b)    asm("mul.rn.f32x2 %0, %1, %2;" : "=l"(d) : "l"(a), "l"(b))

__device__ __forceinline__ float gelu_exact(float x) {
    return 0.5f * x * (1.0f + erff(x * 0.70710678118654752f));
}

// ============ kernel: relative position bias gather ============
// g_bias6[head][n][m] = rpb_table[rpi[n*256+m]*6 + head]
__global__ void bias6_kernel(const int* __restrict__ rpi, const float* __restrict__ rpb) {
    int id = blockIdx.x * 256 + threadIdx.x;       // 6*65536 total
    int head = id >> 16;
    int nm = id & 65535;
    g_bias6[id] = rpb[rpi[nm] * NHEADS + head];
}

// ============ kernel: LayerNorm (+ optional shift/window permute) ============
// mode==1: read xin (token s), write LN to g_xw at window-permuted row (roll -8,-8 then partition)
// mode==0: read g_xr (token s), write LN to g_xw at same row (y0 for MLP)
__global__ __launch_bounds__(192) void ln_kernel(const float* __restrict__ xin,
                                                 const float* __restrict__ gw,
                                                 const float* __restrict__ bw, int mode) {
    int s = blockIdx.x, c = threadIdx.x;
    const float* in = mode ? xin : g_xr;
    float v = in[s * CDIM + c];

    __shared__ float r1[6], r2[6];
    float t = v;
#pragma unroll
    for (int o = 16; o; o >>= 1) t += __shfl_xor_sync(0xffffffffu, t, o);
    if ((c & 31) == 0) r1[c >> 5] = t;
    __syncthreads();
    float mean = (r1[0] + r1[1] + r1[2] + r1[3] + r1[4] + r1[5]) * (1.0f / CDIM);
    float d = v - mean;
    float t2 = d * d;
#pragma unroll
    for (int o = 16; o; o >>= 1) t2 += __shfl_xor_sync(0xffffffffu, t2, o);
    if ((c & 31) == 0) r2[c >> 5] = t2;
    __syncthreads();
    float var = (r2[0] + r2[1] + r2[2] + r2[3] + r2[4] + r2[5]) * (1.0f / CDIM);
    float o = d * rsqrtf(var + 1e-5f) * gw[c] + bw[c];

    int r;
    if (mode) {
        int h = s >> 8, w = s & 255;
        int i = (h + 248) & 255, j = (w + 248) & 255;     // roll(-8,-8): dst (i,j) holds src (i+8,j+8)
        r = (((i >> 4) << 4) + (j >> 4)) * 256 + ((i & 15) << 4) + (j & 15);
    } else {
        r = s;
    }
    g_xw[r * CDIM + c] = o;
}

// ============ tiled f32x2 SGEMM: BM=128, BN=64, BK=8, 256 threads, 8x4 per thread ============
// MODE 0: A=g_xw, scatter epilogue to g_q/g_k/g_v (q scaled)
// MODE 1: A=g_ao, epilogue: window-reverse + unshift + x residual -> g_xr
// MODE 2: A=g_xw(y0), epilogue: GELU -> g_h
// MODE 3: A=g_h, epilogue: + g_xr residual -> outp (d_out)
template <int MODE>
__device__ __forceinline__ void epi_store(float4 v, int r, int o, float4 b4,
                                          const float* __restrict__ aux,
                                          float* __restrict__ outp) {
    v.x += b4.x; v.y += b4.y; v.z += b4.z; v.w += b4.w;
    if (MODE == 0) {
        int wnd = r >> 8, n = r & 255;
        int which = o / 192;
        int rem = o - which * 192;
        int head = rem >> 5, d = rem & 31;
        float* dst = (which == 0) ? g_q : (which == 1) ? g_k : g_v;
        if (which == 0) {
            const float S = 0.17677669529663687f;  // HD^-0.5
            v.x *= S; v.y *= S; v.z *= S; v.w *= S;
        }
        *(float4*)&dst[((wnd * 6 + head) * 256 + n) * 32 + d] = v;
    } else if (MODE == 1) {
        int wnd = r >> 8, n = r & 255;
        int i = ((wnd >> 4) << 4) + (n >> 4);
        int j = ((wnd & 15) << 4) + (n & 15);
        int h = (i + 8) & 255, w = (j + 8) & 255;          // unshift roll(+8,+8)
        int s = h * 256 + w;
        float4 xa = *(const float4*)&aux[s * CDIM + o];
        v.x += xa.x; v.y += xa.y; v.z += xa.z; v.w += xa.w;
        *(float4*)&g_xr[s * CDIM + o] = v;
    } else if (MODE == 2) {
        v.x = gelu_exact(v.x); v.y = gelu_exact(v.y);
        v.z = gelu_exact(v.z); v.w = gelu_exact(v.w);
        *(float4*)&g_h[r * HIDD + o] = v;
    } else {
        float4 xr4 = *(const float4*)&g_xr[r * CDIM + o];
        v.x += xr4.x; v.y += xr4.y; v.z += xr4.z; v.w += xr4.w;
        *(float4*)&outp[r * CDIM + o] = v;
    }
}

template <int MODE>
__global__ __launch_bounds__(256) void gemm_kernel(const float* __restrict__ Bw,
                                                   const float* __restrict__ bias,
                                                   const float* __restrict__ aux,
                                                   float* __restrict__ outp,
                                                   int K, int N) {
    const float* A = (MODE == 0) ? g_xw : (MODE == 1) ? g_ao : (MODE == 2) ? g_xw : g_h;

    __shared__ __align__(16) float As[8 * 132];   // [k][m] transposed, pad 4
    __shared__ __align__(16) float Bs[8 * 68];    // [k][n], pad 4

    int tid = threadIdx.x;
    int m0 = blockIdx.y * 128, n0 = blockIdx.x * 64;
    int tx = tid & 15, ty = tid >> 4;
    int aRow = tid >> 1, aK = (tid & 1) * 4;
    int bK = tid >> 4, bN = (tid & 15) * 4;

    ull acc[4][4];
#pragma unroll
    for (int i = 0; i < 4; i++)
#pragma unroll
        for (int j = 0; j < 4; j++) acc[i][j] = 0ull;

    for (int kt = 0; kt < K; kt += 8) {
        float4 av = *(const float4*)&A[(m0 + aRow) * K + kt + aK];
        As[(aK + 0) * 132 + aRow] = av.x;
        As[(aK + 1) * 132 + aRow] = av.y;
        As[(aK + 2) * 132 + aRow] = av.z;
        As[(aK + 3) * 132 + aRow] = av.w;
        if (tid < 128) {
            float4 bv = *(const float4*)&Bw[(kt + bK) * N + n0 + bN];
            *(float4*)&Bs[bK * 68 + bN] = bv;
        }
        __syncthreads();
#pragma unroll
        for (int k = 0; k < 8; k++) {
            const ulonglong2* ap = (const ulonglong2*)&As[k * 132 + ty * 8];
            ulonglong2 a01 = ap[0], a23 = ap[1];   // 4 m-pairs (8 rows)
            float4 bv = *(const float4*)&Bs[k * 68 + tx * 4];
            ull bd0 = pk2(bv.x, bv.x), bd1 = pk2(bv.y, bv.y);
            ull bd2 = pk2(bv.z, bv.z), bd3 = pk2(bv.w, bv.w);
            FMA2(acc[0][0], a01.x, bd0, acc[0][0]);
            FMA2(acc[0][1], a01.x, bd1, acc[0][1]);
            FMA2(acc[0][2], a01.x, bd2, acc[0][2]);
            FMA2(acc[0][3], a01.x, bd3, acc[0][3]);
            FMA2(acc[1][0], a01.y, bd0, acc[1][0]);
            FMA2(acc[1][1], a01.y, bd1, acc[1][1]);
            FMA2(acc[1][2], a01.y, bd2, acc[1][2]);
            FMA2(acc[1][3], a01.y, bd3, acc[1][3]);
            FMA2(acc[2][0], a23.x, bd0, acc[2][0]);
            FMA2(acc[2][1], a23.x, bd1, acc[2][1]);
            FMA2(acc[2][2], a23.x, bd2, acc[2][2]);
            FMA2(acc[2][3], a23.x, bd3, acc[2][3]);
            FMA2(acc[3][0], a23.y, bd0, acc[3][0]);
            FMA2(acc[3][1], a23.y, bd1, acc[3][1]);
            FMA2(acc[3][2], a23.y, bd2, acc[3][2]);
            FMA2(acc[3][3], a23.y, bd3, acc[3][3]);
        }
        __syncthreads();
    }

    float4 b4 = *(const float4*)&bias[n0 + tx * 4];
    int ocol = n0 + tx * 4;
#pragma unroll
    for (int mp = 0; mp < 4; mp++) {
        float2 c0 = upk(acc[mp][0]), c1 = upk(acc[mp][1]);
        float2 c2 = upk(acc[mp][2]), c3 = upk(acc[mp][3]);
        int rlo = m0 + ty * 8 + mp * 2;
        epi_store<MODE>(make_float4(c0.x, c1.x, c2.x, c3.x), rlo, ocol, b4, aux, outp);
        epi_store<MODE>(make_float4(c0.y, c1.y, c2.y, c3.y), rlo + 1, ocol, b4, aux, outp);
    }
}

// ============ attention: one block per (window, head), flash-style ============
__global__ __launch_bounds__(256) void attn_kernel(const float* __restrict__ mask) {
    extern __shared__ __align__(16) float sm[];
    float* Ks = sm;            // 256*32
    float* Vs = sm + 8192;     // 256*32

    int bid = blockIdx.x;
    int wnd = bid / 6;
    int head = bid - wnd * 6;
    int tid = threadIdx.x;

    const float* Kg = g_k + (size_t)((wnd * 6 + head) * 256) * 32;
    const float* Vg = g_v + (size_t)((wnd * 6 + head) * 256) * 32;
    for (int i = tid; i < 2048; i += 256) {
        ((float4*)Ks)[i] = ((const float4*)Kg)[i];
        ((float4*)Vs)[i] = ((const float4*)Vg)[i];
    }

    ull q2[16];
    {
        const ulonglong2* Qg = (const ulonglong2*)(g_q + (size_t)(((wnd * 6 + head) * 256) + tid) * 32);
#pragma unroll
        for (int p = 0; p < 8; p++) {
            ulonglong2 qq = Qg[p];
            q2[2 * p] = qq.x;
            q2[2 * p + 1] = qq.y;
        }
    }
    __syncthreads();

    const float* brow = g_bias6 + head * 65536 + tid * 256;
    const float* mrow = mask + (size_t)wnd * 65536 + tid * 256;

    ull acc2[16];
#pragma unroll
    for (int p = 0; p < 16; p++) acc2[p] = 0ull;
    float mx = -1e30f, denom = 0.0f;

    for (int t = 0; t < 8; t++) {
        float s[32];
        float tmax = -1e30f;
#pragma unroll
        for (int mm = 0; mm < 32; mm++) {
            int m = t * 32 + mm;
            const ulonglong2* k2 = (const ulonglong2*)(Ks + m * 32);
            ull da = 0ull, db = 0ull;   // two accumulators to break the dep chain
#pragma unroll
            for (int p = 0; p < 8; p++) {
                ulonglong2 kk = k2[p];
                FMA2(da, q2[2 * p], kk.x, da);
                FMA2(db, q2[2 * p + 1], kk.y, db);
            }
            float2 fa = upk(da), fb = upk(db);
            float sc = (fa.x + fa.y) + (fb.x + fb.y) + brow[m] + mrow[m];
            s[mm] = sc;
            tmax = fmaxf(tmax, sc);
        }
        float nm = fmaxf(mx, tmax);
        float scale = __expf(mx - nm);
        denom *= scale;
        ull sc2 = pk2(scale, scale);
#pragma unroll
        for (int p = 0; p < 16; p++) MUL2(acc2[p], acc2[p], sc2);
#pragma unroll
        for (int mm = 0; mm < 32; mm++) {
            int m = t * 32 + mm;
            float p = __expf(s[mm] - nm);
            denom += p;
            ull p2 = pk2(p, p);
            const ulonglong2* v2 = (const ulonglong2*)(Vs + m * 32);
#pragma unroll
            for (int q = 0; q < 8; q++) {
                ulonglong2 vv = v2[q];
                FMA2(acc2[2 * q], p2, vv.x, acc2[2 * q]);
                FMA2(acc2[2 * q + 1], p2, vv.y, acc2[2 * q + 1]);
            }
        }
        mx = nm;
    }

    float inv = 1.0f / denom;
    float* op = g_ao + (size_t)(wnd * 256 + tid) * CDIM + head * 32;
#pragma unroll
    for (int p = 0; p < 8; p++) {
        float2 a = upk(acc2[2 * p]);
        float2 b = upk(acc2[2 * p + 1]);
        *(float4*)&op[p * 4] = make_float4(a.x * inv, a.y * inv, b.x * inv, b.y * inv);
    }
}

// ============ host launcher ============
extern "C" void kernel_launch(void* const* d_in, const int* in_sizes, int n_in,
                              void* d_out, int out_size) {
    const float* x     = (const float*)d_in[0];
    const int*   rpi   = (const int*)d_in[1];
    const float* mask  = (const float*)d_in[2];
    const float* n1g   = (const float*)d_in[3];
    const float* n1b   = (const float*)d_in[4];
    const float* qkvw  = (const float*)d_in[5];
    const float* qkvb  = (const float*)d_in[6];
    const float* rpb   = (const float*)d_in[7];
    const float* projw = (const float*)d_in[8];
    const float* projb = (const float*)d_in[9];
    const float* n2g   = (const float*)d_in[10];
    const float* n2b   = (const float*)d_in[11];
    const float* fc1w  = (const float*)d_in[12];
    const float* fc1b  = (const float*)d_in[13];
    const float* fc2w  = (const float*)d_in[14];
    const float* fc2b  = (const float*)d_in[15];
    float* out = (float*)d_out;

    cudaFuncSetAttribute(attn_kernel, cudaFuncAttributeMaxDynamicSharedMemorySize, 65536);

    bias6_kernel<<<1536, 256>>>(rpi, rpb);
    ln_kernel<<<65536, 192>>>(x, n1g, n1b, 1);                               // LN1 + shift + partition
    gemm_kernel<0><<<dim3(9, 512), 256>>>(qkvw, qkvb, nullptr, nullptr, 192, 576);   // QKV
    attn_kernel<<<1536, 256, 65536>>>(mask);                                 // windowed attention
    gemm_kernel<1><<<dim3(3, 512), 256>>>(projw, projb, x, nullptr, 192, 192);       // proj + reverse + resid
    ln_kernel<<<65536, 192>>>(x, n2g, n2b, 0);                               // LN2 (reads g_xr)
    gemm_kernel<2><<<dim3(12, 512), 256>>>(fc1w, fc1b, nullptr, nullptr, 192, 768);  // fc1 + GELU
    gemm_kernel<3><<<dim3(3, 512), 256>>>(fc2w, fc2b, nullptr, out, 768, 192);       // fc2 + resid -> out
}

// round 5
// speedup vs baseline: 1.0019x; 1.0019x over previous
#include <cuda_runtime.h>
#include <math.h>

#define LTOK 65536          // H*W tokens
#define CDIM 192
#define NHEADS 6
#define HDIM 32
#define HIDD 768

typedef unsigned long long ull;

// -------- scratch (static device globals; no allocation) --------
__device__ float g_xw[LTOK * CDIM];       // LN1'd, shifted, window-partitioned; reused as y0 after QKV
__device__ float g_q[LTOK * CDIM];        // [win,head,n,d]
__device__ float g_k[LTOK * CDIM];
__device__ float g_v[LTOK * CDIM];
__device__ float g_ao[LTOK * CDIM];       // attention out, window order, col = head*32+d
__device__ float g_xr[LTOK * CDIM];       // first residual, token order
__device__ float g_h[LTOK * HIDD];        // MLP hidden
__device__ float g_bias6[NHEADS * 256 * 256];

// -------- packed f32x2 helpers --------
__device__ __forceinline__ ull pk2(float lo, float hi) {
    ull r; asm("mov.b64 %0, {%1,%2};" : "=l"(r) : "f"(lo), "f"(hi)); return r;
}
__device__ __forceinline__ float2 upk(ull v) {
    float2 f; asm("mov.b64 {%0,%1}, %2;" : "=f"(f.x), "=f"(f.y) : "l"(v)); return f;
}
#define FMA2(d, a, b, c) asm("fma.rn.f32x2 %0, %1, %2, %3;" : "=l"(d) : "l"(a), "l"(b), "l"(c))
#define MUL2(d, a, b)    asm("mul.rn.f32x2 %0, %1, %2;" : "=l"(d) : "l"(a), "l"(b))

__device__ __forceinline__ float gelu_exact(float x) {
    return 0.5f * x * (1.0f + erff(x * 0.70710678118654752f));
}

// ============ kernel: relative position bias gather ============
// g_bias6[head][n][m] = rpb_table[rpi[n*256+m]*6 + head]
__global__ void bias6_kernel(const int* __restrict__ rpi, const float* __restrict__ rpb) {
    int id = blockIdx.x * 256 + threadIdx.x;       // 6*65536 total
    int head = id >> 16;
    int nm = id & 65535;
    g_bias6[id] = rpb[rpi[nm] * NHEADS + head];
}

// ============ kernel: LayerNorm (+ optional shift/window permute) ============
// mode==1: read xin (token s), write LN to g_xw at window-permuted row (roll -8,-8 then partition)
// mode==0: read g_xr (token s), write LN to g_xw at same row (y0 for MLP)
__global__ __launch_bounds__(192) void ln_kernel(const float* __restrict__ xin,
                                                 const float* __restrict__ gw,
                                                 const float* __restrict__ bw, int mode) {
    int s = blockIdx.x, c = threadIdx.x;
    const float* in = mode ? xin : g_xr;
    float v = in[s * CDIM + c];

    __shared__ float r1[6], r2[6];
    float t = v;
#pragma unroll
    for (int o = 16; o; o >>= 1) t += __shfl_xor_sync(0xffffffffu, t, o);
    if ((c & 31) == 0) r1[c >> 5] = t;
    __syncthreads();
    float mean = (r1[0] + r1[1] + r1[2] + r1[3] + r1[4] + r1[5]) * (1.0f / CDIM);
    float d = v - mean;
    float t2 = d * d;
#pragma unroll
    for (int o = 16; o; o >>= 1) t2 += __shfl_xor_sync(0xffffffffu, t2, o);
    if ((c & 31) == 0) r2[c >> 5] = t2;
    __syncthreads();
    float var = (r2[0] + r2[1] + r2[2] + r2[3] + r2[4] + r2[5]) * (1.0f / CDIM);
    float o = d * rsqrtf(var + 1e-5f) * gw[c] + bw[c];

    int r;
    if (mode) {
        int h = s >> 8, w = s & 255;
        int i = (h + 248) & 255, j = (w + 248) & 255;     // roll(-8,-8): dst (i,j) holds src (i+8,j+8)
        r = (((i >> 4) << 4) + (j >> 4)) * 256 + ((i & 15) << 4) + (j & 15);
    } else {
        r = s;
    }
    g_xw[r * CDIM + c] = o;
}

// ============ tiled f32x2 SGEMM: BM=128, BN=64, BK=8, 256 threads, 8x4 per thread ============
// MODE 0: A=g_xw, scatter epilogue to g_q/g_k/g_v (q scaled)
// MODE 1: A=g_ao, epilogue: window-reverse + unshift + x residual -> g_xr
// MODE 2: A=g_xw(y0), epilogue: GELU -> g_h
// MODE 3: A=g_h, epilogue: + g_xr residual -> outp (d_out)
template <int MODE>
__device__ __forceinline__ void epi_store(float4 v, int r, int o, float4 b4,
                                          const float* __restrict__ aux,
                                          float* __restrict__ outp) {
    v.x += b4.x; v.y += b4.y; v.z += b4.z; v.w += b4.w;
    if (MODE == 0) {
        int wnd = r >> 8, n = r & 255;
        int which = o / 192;
        int rem = o - which * 192;
        int head = rem >> 5, d = rem & 31;
        float* dst = (which == 0) ? g_q : (which == 1) ? g_k : g_v;
        if (which == 0) {
            const float S = 0.17677669529663687f;  // HD^-0.5
            v.x *= S; v.y *= S; v.z *= S; v.w *= S;
        }
        *(float4*)&dst[((wnd * 6 + head) * 256 + n) * 32 + d] = v;
    } else if (MODE == 1) {
        int wnd = r >> 8, n = r & 255;
        int i = ((wnd >> 4) << 4) + (n >> 4);
        int j = ((wnd & 15) << 4) + (n & 15);
        int h = (i + 8) & 255, w = (j + 8) & 255;          // unshift roll(+8,+8)
        int s = h * 256 + w;
        float4 xa = *(const float4*)&aux[s * CDIM + o];
        v.x += xa.x; v.y += xa.y; v.z += xa.z; v.w += xa.w;
        *(float4*)&g_xr[s * CDIM + o] = v;
    } else if (MODE == 2) {
        v.x = gelu_exact(v.x); v.y = gelu_exact(v.y);
        v.z = gelu_exact(v.z); v.w = gelu_exact(v.w);
        *(float4*)&g_h[r * HIDD + o] = v;
    } else {
        float4 xr4 = *(const float4*)&g_xr[r * CDIM + o];
        v.x += xr4.x; v.y += xr4.y; v.z += xr4.z; v.w += xr4.w;
        *(float4*)&outp[r * CDIM + o] = v;
    }
}

template <int MODE>
__global__ __launch_bounds__(256) void gemm_kernel(const float* __restrict__ Bw,
                                                   const float* __restrict__ bias,
                                                   const float* __restrict__ aux,
                                                   float* __restrict__ outp,
                                                   int K, int N) {
    const float* A = (MODE == 0) ? g_xw : (MODE == 1) ? g_ao : (MODE == 2) ? g_xw : g_h;

    __shared__ __align__(16) float As[8 * 132];   // [k][m] transposed, pad 4
    __shared__ __align__(16) float Bs[8 * 68];    // [k][n], pad 4

    int tid = threadIdx.x;
    int m0 = blockIdx.y * 128, n0 = blockIdx.x * 64;
    int tx = tid & 15, ty = tid >> 4;
    int aRow = tid >> 1, aK = (tid & 1) * 4;
    int bK = tid >> 4, bN = (tid & 15) * 4;

    ull acc[4][4];
#pragma unroll
    for (int i = 0; i < 4; i++)
#pragma unroll
        for (int j = 0; j < 4; j++) acc[i][j] = 0ull;

    for (int kt = 0; kt < K; kt += 8) {
        float4 av = *(const float4*)&A[(m0 + aRow) * K + kt + aK];
        As[(aK + 0) * 132 + aRow] = av.x;
        As[(aK + 1) * 132 + aRow] = av.y;
        As[(aK + 2) * 132 + aRow] = av.z;
        As[(aK + 3) * 132 + aRow] = av.w;
        if (tid < 128) {
            float4 bv = *(const float4*)&Bw[(kt + bK) * N + n0 + bN];
            *(float4*)&Bs[bK * 68 + bN] = bv;
        }
        __syncthreads();
#pragma unroll
        for (int k = 0; k < 8; k++) {
            const ulonglong2* ap = (const ulonglong2*)&As[k * 132 + ty * 8];
            ulonglong2 a01 = ap[0], a23 = ap[1];   // 4 m-pairs (8 rows)
            float4 bv = *(const float4*)&Bs[k * 68 + tx * 4];
            ull bd0 = pk2(bv.x, bv.x), bd1 = pk2(bv.y, bv.y);
            ull bd2 = pk2(bv.z, bv.z), bd3 = pk2(bv.w, bv.w);
            FMA2(acc[0][0], a01.x, bd0, acc[0][0]);
            FMA2(acc[0][1], a01.x, bd1, acc[0][1]);
            FMA2(acc[0][2], a01.x, bd2, acc[0][2]);
            FMA2(acc[0][3], a01.x, bd3, acc[0][3]);
            FMA2(acc[1][0], a01.y, bd0, acc[1][0]);
            FMA2(acc[1][1], a01.y, bd1, acc[1][1]);
            FMA2(acc[1][2], a01.y, bd2, acc[1][2]);
            FMA2(acc[1][3], a01.y, bd3, acc[1][3]);
            FMA2(acc[2][0], a23.x, bd0, acc[2][0]);
            FMA2(acc[2][1], a23.x, bd1, acc[2][1]);
            FMA2(acc[2][2], a23.x, bd2, acc[2][2]);
            FMA2(acc[2][3], a23.x, bd3, acc[2][3]);
            FMA2(acc[3][0], a23.y, bd0, acc[3][0]);
            FMA2(acc[3][1], a23.y, bd1, acc[3][1]);
            FMA2(acc[3][2], a23.y, bd2, acc[3][2]);
            FMA2(acc[3][3], a23.y, bd3, acc[3][3]);
        }
        __syncthreads();
    }

    float4 b4 = *(const float4*)&bias[n0 + tx * 4];
    int ocol = n0 + tx * 4;
#pragma unroll
    for (int mp = 0; mp < 4; mp++) {
        float2 c0 = upk(acc[mp][0]), c1 = upk(acc[mp][1]);
        float2 c2 = upk(acc[mp][2]), c3 = upk(acc[mp][3]);
        int rlo = m0 + ty * 8 + mp * 2;
        epi_store<MODE>(make_float4(c0.x, c1.x, c2.x, c3.x), rlo, ocol, b4, aux, outp);
        epi_store<MODE>(make_float4(c0.y, c1.y, c2.y, c3.y), rlo + 1, ocol, b4, aux, outp);
    }
}

// ============ attention: one block per (window, head), flash-style ============
__global__ __launch_bounds__(256) void attn_kernel(const float* __restrict__ mask) {
    extern __shared__ __align__(16) float sm[];
    float* Ks = sm;            // 256*32
    float* Vs = sm + 8192;     // 256*32

    int bid = blockIdx.x;
    int wnd = bid / 6;
    int head = bid - wnd * 6;
    int tid = threadIdx.x;

    const float* Kg = g_k + (size_t)((wnd * 6 + head) * 256) * 32;
    const float* Vg = g_v + (size_t)((wnd * 6 + head) * 256) * 32;
    for (int i = tid; i < 2048; i += 256) {
        ((float4*)Ks)[i] = ((const float4*)Kg)[i];
        ((float4*)Vs)[i] = ((const float4*)Vg)[i];
    }

    ull q2[16];
    {
        const ulonglong2* Qg = (const ulonglong2*)(g_q + (size_t)(((wnd * 6 + head) * 256) + tid) * 32);
#pragma unroll
        for (int p = 0; p < 8; p++) {
            ulonglong2 qq = Qg[p];
            q2[2 * p] = qq.x;
            q2[2 * p + 1] = qq.y;
        }
    }
    __syncthreads();

    const float* brow = g_bias6 + head * 65536 + tid * 256;
    const float* mrow = mask + (size_t)wnd * 65536 + tid * 256;

    ull acc2[16];
#pragma unroll
    for (int p = 0; p < 16; p++) acc2[p] = 0ull;
    float mx = -1e30f, denom = 0.0f;

    for (int t = 0; t < 8; t++) {
        float s[32];
        float tmax = -1e30f;
#pragma unroll
        for (int mm = 0; mm < 32; mm++) {
            int m = t * 32 + mm;
            const ulonglong2* k2 = (const ulonglong2*)(Ks + m * 32);
            ull da = 0ull, db = 0ull;   // two accumulators to break the dep chain
#pragma unroll
            for (int p = 0; p < 8; p++) {
                ulonglong2 kk = k2[p];
                FMA2(da, q2[2 * p], kk.x, da);
                FMA2(db, q2[2 * p + 1], kk.y, db);
            }
            float2 fa = upk(da), fb = upk(db);
            float sc = (fa.x + fa.y) + (fb.x + fb.y) + brow[m] + mrow[m];
            s[mm] = sc;
            tmax = fmaxf(tmax, sc);
        }
        float nm = fmaxf(mx, tmax);
        float scale = __expf(mx - nm);
        denom *= scale;
        ull sc2 = pk2(scale, scale);
#pragma unroll
        for (int p = 0; p < 16; p++) MUL2(acc2[p], acc2[p], sc2);
#pragma unroll
        for (int mm = 0; mm < 32; mm++) {
            int m = t * 32 + mm;
            float p = __expf(s[mm] - nm);
            denom += p;
            ull p2 = pk2(p, p);
            const ulonglong2* v2 = (const ulonglong2*)(Vs + m * 32);
#pragma unroll
            for (int q = 0; q < 8; q++) {
                ulonglong2 vv = v2[q];
                FMA2(acc2[2 * q], p2, vv.x, acc2[2 * q]);
                FMA2(acc2[2 * q + 1], p2, vv.y, acc2[2 * q + 1]);
            }
        }
        mx = nm;
    }

    float inv = 1.0f / denom;
    float* op = g_ao + (size_t)(wnd * 256 + tid) * CDIM + head * 32;
#pragma unroll
    for (int p = 0; p < 8; p++) {
        float2 a = upk(acc2[2 * p]);
        float2 b = upk(acc2[2 * p + 1]);
        *(float4*)&op[p * 4] = make_float4(a.x * inv, a.y * inv, b.x * inv, b.y * inv);
    }
}

// ============ host launcher ============
extern "C" void kernel_launch(void* const* d_in, const int* in_sizes, int n_in,
                              void* d_out, int out_size) {
    const float* x     = (const float*)d_in[0];
    const int*   rpi   = (const int*)d_in[1];
    const float* mask  = (const float*)d_in[2];
    const float* n1g   = (const float*)d_in[3];
    const float* n1b   = (const float*)d_in[4];
    const float* qkvw  = (const float*)d_in[5];
    const float* qkvb  = (const float*)d_in[6];
    const float* rpb   = (const float*)d_in[7];
    const float* projw = (const float*)d_in[8];
    const float* projb = (const float*)d_in[9];
    const float* n2g   = (const float*)d_in[10];
    const float* n2b   = (const float*)d_in[11];
    const float* fc1w  = (const float*)d_in[12];
    const float* fc1b  = (const float*)d_in[13];
    const float* fc2w  = (const float*)d_in[14];
    const float* fc2b  = (const float*)d_in[15];
    float* out = (float*)d_out;

    cudaFuncSetAttribute(attn_kernel, cudaFuncAttributeMaxDynamicSharedMemorySize, 65536);

    bias6_kernel<<<1536, 256>>>(rpi, rpb);
    ln_kernel<<<65536, 192>>>(x, n1g, n1b, 1);                               // LN1 + shift + partition
    gemm_kernel<0><<<dim3(9, 512), 256>>>(qkvw, qkvb, nullptr, nullptr, 192, 576);   // QKV
    attn_kernel<<<1536, 256, 65536>>>(mask);                                 // windowed attention
    gemm_kernel<1><<<dim3(3, 512), 256>>>(projw, projb, x, nullptr, 192, 192);       // proj + reverse + resid
    ln_kernel<<<65536, 192>>>(x, n2g, n2b, 0);                               // LN2 (reads g_xr)
    gemm_kernel<2><<<dim3(12, 512), 256>>>(fc1w, fc1b, nullptr, nullptr, 192, 768);  // fc1 + GELU
    gemm_kernel<3><<<dim3(3, 512), 256>>>(fc2w, fc2b, nullptr, out, 768, 192);       // fc2 + resid -> out
}

// round 6
// speedup vs baseline: 1.0039x; 1.0020x over previous
#include <cuda_runtime.h>
#include <math.h>

#define LTOK 65536          // H*W tokens
#define CDIM 192
#define NHEADS 6
#define HDIM 32
#define HIDD 768

typedef unsigned long long ull;

// -------- scratch (static device globals; no allocation) --------
__device__ float g_xw[LTOK * CDIM];       // LN1'd, shifted, window-partitioned; reused as y0 after QKV
__device__ float g_q[LTOK * CDIM];        // [win,head,n,d]
__device__ float g_k[LTOK * CDIM];
__device__ float g_v[LTOK * CDIM];
__device__ float g_ao[LTOK * CDIM];       // attention out, window order, col = head*32+d
__device__ float g_xr[LTOK * CDIM];       // first residual, token order
__device__ float g_h[LTOK * HIDD];        // MLP hidden
__device__ float g_bias6[NHEADS * 256 * 256];

// -------- packed f32x2 helpers --------
__device__ __forceinline__ ull pk2(float lo, float hi) {
    ull r; asm("mov.b64 %0, {%1,%2};" : "=l"(r) : "f"(lo), "f"(hi)); return r;
}
__device__ __forceinline__ float2 upk(ull v) {
    float2 f; asm("mov.b64 {%0,%1}, %2;" : "=f"(f.x), "=f"(f.y) : "l"(v)); return f;
}
#define FMA2(d, a, b, c) asm("fma.rn.f32x2 %0, %1, %2, %3;" : "=l"(d) : "l"(a), "l"(b), "l"(c))
#define MUL2(d, a, b)    asm("mul.rn.f32x2 %0, %1, %2;" : "=l"(d) : "l"(a), "l"(b))

__device__ __forceinline__ float gelu_exact(float x) {
    return 0.5f * x * (1.0f + erff(x * 0.70710678118654752f));
}

// ============ kernel: relative position bias gather ============
// g_bias6[head][n][m] = rpb_table[rpi[n*256+m]*6 + head]
__global__ void bias6_kernel(const int* __restrict__ rpi, const float* __restrict__ rpb) {
    int id = blockIdx.x * 256 + threadIdx.x;       // 6*65536 total
    int head = id >> 16;
    int nm = id & 65535;
    g_bias6[id] = rpb[rpi[nm] * NHEADS + head];
}

// ============ kernel: LayerNorm (+ optional shift/window permute) ============
// mode==1: read xin (token s), write LN to g_xw at window-permuted row (roll -8,-8 then partition)
// mode==0: read g_xr (token s), write LN to g_xw at same row (y0 for MLP)
__global__ __launch_bounds__(192) void ln_kernel(const float* __restrict__ xin,
                                                 const float* __restrict__ gw,
                                                 const float* __restrict__ bw, int mode) {
    int s = blockIdx.x, c = threadIdx.x;
    const float* in = mode ? xin : g_xr;
    float v = in[s * CDIM + c];

    __shared__ float r1[6], r2[6];
    float t = v;
#pragma unroll
    for (int o = 16; o; o >>= 1) t += __shfl_xor_sync(0xffffffffu, t, o);
    if ((c & 31) == 0) r1[c >> 5] = t;
    __syncthreads();
    float mean = (r1[0] + r1[1] + r1[2] + r1[3] + r1[4] + r1[5]) * (1.0f / CDIM);
    float d = v - mean;
    float t2 = d * d;
#pragma unroll
    for (int o = 16; o; o >>= 1) t2 += __shfl_xor_sync(0xffffffffu, t2, o);
    if ((c & 31) == 0) r2[c >> 5] = t2;
    __syncthreads();
    float var = (r2[0] + r2[1] + r2[2] + r2[3] + r2[4] + r2[5]) * (1.0f / CDIM);
    float o = d * rsqrtf(var + 1e-5f) * gw[c] + bw[c];

    int r;
    if (mode) {
        int h = s >> 8, w = s & 255;
        int i = (h + 248) & 255, j = (w + 248) & 255;     // roll(-8,-8): dst (i,j) holds src (i+8,j+8)
        r = (((i >> 4) << 4) + (j >> 4)) * 256 + ((i & 15) << 4) + (j & 15);
    } else {
        r = s;
    }
    g_xw[r * CDIM + c] = o;
}

// ============ tiled f32x2 SGEMM: BM=128, BN=64, BK=8, 256 threads, 8x4 per thread ============
// MODE 0: A=g_xw, scatter epilogue to g_q/g_k/g_v (q scaled)
// MODE 1: A=g_ao, epilogue: window-reverse + unshift + x residual -> g_xr
// MODE 2: A=g_xw(y0), epilogue: GELU -> g_h
// MODE 3: A=g_h, epilogue: + g_xr residual -> outp (d_out)
template <int MODE>
__device__ __forceinline__ void epi_store(float4 v, int r, int o, float4 b4,
                                          const float* __restrict__ aux,
                                          float* __restrict__ outp) {
    v.x += b4.x; v.y += b4.y; v.z += b4.z; v.w += b4.w;
    if (MODE == 0) {
        int wnd = r >> 8, n = r & 255;
        int which = o / 192;
        int rem = o - which * 192;
        int head = rem >> 5, d = rem & 31;
        float* dst = (which == 0) ? g_q : (which == 1) ? g_k : g_v;
        if (which == 0) {
            const float S = 0.17677669529663687f;  // HD^-0.5
            v.x *= S; v.y *= S; v.z *= S; v.w *= S;
        }
        *(float4*)&dst[((wnd * 6 + head) * 256 + n) * 32 + d] = v;
    } else if (MODE == 1) {
        int wnd = r >> 8, n = r & 255;
        int i = ((wnd >> 4) << 4) + (n >> 4);
        int j = ((wnd & 15) << 4) + (n & 15);
        int h = (i + 8) & 255, w = (j + 8) & 255;          // unshift roll(+8,+8)
        int s = h * 256 + w;
        float4 xa = *(const float4*)&aux[s * CDIM + o];
        v.x += xa.x; v.y += xa.y; v.z += xa.z; v.w += xa.w;
        *(float4*)&g_xr[s * CDIM + o] = v;
    } else if (MODE == 2) {
        v.x = gelu_exact(v.x); v.y = gelu_exact(v.y);
        v.z = gelu_exact(v.z); v.w = gelu_exact(v.w);
        *(float4*)&g_h[r * HIDD + o] = v;
    } else {
        float4 xr4 = *(const float4*)&g_xr[r * CDIM + o];
        v.x += xr4.x; v.y += xr4.y; v.z += xr4.z; v.w += xr4.w;
        *(float4*)&outp[r * CDIM + o] = v;
    }
}

template <int MODE>
__global__ __launch_bounds__(256) void gemm_kernel(const float* __restrict__ Bw,
                                                   const float* __restrict__ bias,
                                                   const float* __restrict__ aux,
                                                   float* __restrict__ outp,
                                                   int K, int N) {
    const float* A = (MODE == 0) ? g_xw : (MODE == 1) ? g_ao : (MODE == 2) ? g_xw : g_h;

    __shared__ __align__(16) float As[8 * 132];   // [k][m] transposed, pad 4
    __shared__ __align__(16) float Bs[8 * 68];    // [k][n], pad 4

    int tid = threadIdx.x;
    int m0 = blockIdx.y * 128, n0 = blockIdx.x * 64;
    int tx = tid & 15, ty = tid >> 4;
    int aRow = tid >> 1, aK = (tid & 1) * 4;
    int bK = tid >> 4, bN = (tid & 15) * 4;

    ull acc[4][4];
#pragma unroll
    for (int i = 0; i < 4; i++)
#pragma unroll
        for (int j = 0; j < 4; j++) acc[i][j] = 0ull;

    for (int kt = 0; kt < K; kt += 8) {
        float4 av = *(const float4*)&A[(m0 + aRow) * K + kt + aK];
        As[(aK + 0) * 132 + aRow] = av.x;
        As[(aK + 1) * 132 + aRow] = av.y;
        As[(aK + 2) * 132 + aRow] = av.z;
        As[(aK + 3) * 132 + aRow] = av.w;
        if (tid < 128) {
            float4 bv = *(const float4*)&Bw[(kt + bK) * N + n0 + bN];
            *(float4*)&Bs[bK * 68 + bN] = bv;
        }
        __syncthreads();
#pragma unroll
        for (int k = 0; k < 8; k++) {
            const ulonglong2* ap = (const ulonglong2*)&As[k * 132 + ty * 8];
            ulonglong2 a01 = ap[0], a23 = ap[1];   // 4 m-pairs (8 rows)
            float4 bv = *(const float4*)&Bs[k * 68 + tx * 4];
            ull bd0 = pk2(bv.x, bv.x), bd1 = pk2(bv.y, bv.y);
            ull bd2 = pk2(bv.z, bv.z), bd3 = pk2(bv.w, bv.w);
            FMA2(acc[0][0], a01.x, bd0, acc[0][0]);
            FMA2(acc[0][1], a01.x, bd1, acc[0][1]);
            FMA2(acc[0][2], a01.x, bd2, acc[0][2]);
            FMA2(acc[0][3], a01.x, bd3, acc[0][3]);
            FMA2(acc[1][0], a01.y, bd0, acc[1][0]);
            FMA2(acc[1][1], a01.y, bd1, acc[1][1]);
            FMA2(acc[1][2], a01.y, bd2, acc[1][2]);
            FMA2(acc[1][3], a01.y, bd3, acc[1][3]);
            FMA2(acc[2][0], a23.x, bd0, acc[2][0]);
            FMA2(acc[2][1], a23.x, bd1, acc[2][1]);
            FMA2(acc[2][2], a23.x, bd2, acc[2][2]);
            FMA2(acc[2][3], a23.x, bd3, acc[2][3]);
            FMA2(acc[3][0], a23.y, bd0, acc[3][0]);
            FMA2(acc[3][1], a23.y, bd1, acc[3][1]);
            FMA2(acc[3][2], a23.y, bd2, acc[3][2]);
            FMA2(acc[3][3], a23.y, bd3, acc[3][3]);
        }
        __syncthreads();
    }

    float4 b4 = *(const float4*)&bias[n0 + tx * 4];
    int ocol = n0 + tx * 4;
#pragma unroll
    for (int mp = 0; mp < 4; mp++) {
        float2 c0 = upk(acc[mp][0]), c1 = upk(acc[mp][1]);
        float2 c2 = upk(acc[mp][2]), c3 = upk(acc[mp][3]);
        int rlo = m0 + ty * 8 + mp * 2;
        epi_store<MODE>(make_float4(c0.x, c1.x, c2.x, c3.x), rlo, ocol, b4, aux, outp);
        epi_store<MODE>(make_float4(c0.y, c1.y, c2.y, c3.y), rlo + 1, ocol, b4, aux, outp);
    }
}

// ============ attention: one block per (window, head), flash-style ============
__global__ __launch_bounds__(256) void attn_kernel(const float* __restrict__ mask) {
    extern __shared__ __align__(16) float sm[];
    float* Ks = sm;            // 256*32
    float* Vs = sm + 8192;     // 256*32

    int bid = blockIdx.x;
    int wnd = bid / 6;
    int head = bid - wnd * 6;
    int tid = threadIdx.x;

    const float* Kg = g_k + (size_t)((wnd * 6 + head) * 256) * 32;
    const float* Vg = g_v + (size_t)((wnd * 6 + head) * 256) * 32;
    for (int i = tid; i < 2048; i += 256) {
        ((float4*)Ks)[i] = ((const float4*)Kg)[i];
        ((float4*)Vs)[i] = ((const float4*)Vg)[i];
    }

    ull q2[16];
    {
        const ulonglong2* Qg = (const ulonglong2*)(g_q + (size_t)(((wnd * 6 + head) * 256) + tid) * 32);
#pragma unroll
        for (int p = 0; p < 8; p++) {
            ulonglong2 qq = Qg[p];
            q2[2 * p] = qq.x;
            q2[2 * p + 1] = qq.y;
        }
    }
    __syncthreads();

    const float* brow = g_bias6 + head * 65536 + tid * 256;
    const float* mrow = mask + (size_t)wnd * 65536 + tid * 256;

    ull acc2[16];
#pragma unroll
    for (int p = 0; p < 16; p++) acc2[p] = 0ull;
    float mx = -1e30f, denom = 0.0f;

    for (int t = 0; t < 8; t++) {
        float s[32];
        float tmax = -1e30f;
#pragma unroll
        for (int mm = 0; mm < 32; mm++) {
            int m = t * 32 + mm;
            const ulonglong2* k2 = (const ulonglong2*)(Ks + m * 32);
            ull da = 0ull, db = 0ull;   // two accumulators to break the dep chain
#pragma unroll
            for (int p = 0; p < 8; p++) {
                ulonglong2 kk = k2[p];
                FMA2(da, q2[2 * p], kk.x, da);
                FMA2(db, q2[2 * p + 1], kk.y, db);
            }
            float2 fa = upk(da), fb = upk(db);
            float sc = (fa.x + fa.y) + (fb.x + fb.y) + brow[m] + mrow[m];
            s[mm] = sc;
            tmax = fmaxf(tmax, sc);
        }
        float nm = fmaxf(mx, tmax);
        float scale = __expf(mx - nm);
        denom *= scale;
        ull sc2 = pk2(scale, scale);
#pragma unroll
        for (int p = 0; p < 16; p++) MUL2(acc2[p], acc2[p], sc2);
#pragma unroll
        for (int mm = 0; mm < 32; mm++) {
            int m = t * 32 + mm;
            float p = __expf(s[mm] - nm);
            denom += p;
            ull p2 = pk2(p, p);
            const ulonglong2* v2 = (const ulonglong2*)(Vs + m * 32);
#pragma unroll
            for (int q = 0; q < 8; q++) {
                ulonglong2 vv = v2[q];
                FMA2(acc2[2 * q], p2, vv.x, acc2[2 * q]);
                FMA2(acc2[2 * q + 1], p2, vv.y, acc2[2 * q + 1]);
            }
        }
        mx = nm;
    }

    float inv = 1.0f / denom;
    float* op = g_ao + (size_t)(wnd * 256 + tid) * CDIM + head * 32;
#pragma unroll
    for (int p = 0; p < 8; p++) {
        float2 a = upk(acc2[2 * p]);
        float2 b = upk(acc2[2 * p + 1]);
        *(float4*)&op[p * 4] = make_float4(a.x * inv, a.y * inv, b.x * inv, b.y * inv);
    }
}

// ============ host launcher ============
extern "C" void kernel_launch(void* const* d_in, const int* in_sizes, int n_in,
                              void* d_out, int out_size) {
    const float* x     = (const float*)d_in[0];
    const int*   rpi   = (const int*)d_in[1];
    const float* mask  = (const float*)d_in[2];
    const float* n1g   = (const float*)d_in[3];
    const float* n1b   = (const float*)d_in[4];
    const float* qkvw  = (const float*)d_in[5];
    const float* qkvb  = (const float*)d_in[6];
    const float* rpb   = (const float*)d_in[7];
    const float* projw = (const float*)d_in[8];
    const float* projb = (const float*)d_in[9];
    const float* n2g   = (const float*)d_in[10];
    const float* n2b   = (const float*)d_in[11];
    const float* fc1w  = (const float*)d_in[12];
    const float* fc1b  = (const float*)d_in[13];
    const float* fc2w  = (const float*)d_in[14];
    const float* fc2b  = (const float*)d_in[15];
    float* out = (float*)d_out;

    cudaFuncSetAttribute(attn_kernel, cudaFuncAttributeMaxDynamicSharedMemorySize, 65536);

    bias6_kernel<<<1536, 256>>>(rpi, rpb);
    ln_kernel<<<65536, 192>>>(x, n1g, n1b, 1);                               // LN1 + shift + partition
    gemm_kernel<0><<<dim3(9, 512), 256>>>(qkvw, qkvb, nullptr, nullptr, 192, 576);   // QKV
    attn_kernel<<<1536, 256, 65536>>>(mask);                                 // windowed attention
    gemm_kernel<1><<<dim3(3, 512), 256>>>(projw, projb, x, nullptr, 192, 192);       // proj + reverse + resid
    ln_kernel<<<65536, 192>>>(x, n2g, n2b, 0);                               // LN2 (reads g_xr)
    gemm_kernel<2><<<dim3(12, 512), 256>>>(fc1w, fc1b, nullptr, nullptr, 192, 768);  // fc1 + GELU
    gemm_kernel<3><<<dim3(3, 512), 256>>>(fc2w, fc2b, nullptr, out, 768, 192);       // fc2 + resid -> out
}